// round 1
// baseline (speedup 1.0000x reference)
#include <cuda_runtime.h>

// Conv3dFFT: per-channel 64^3 circular convolution via FFT, odd-index stride-2 output.
// x: (1,32,62,62,62) f32, weight: (16,32,64,64,64) f32 -> out: (16,32,31,31,31) f32
//
// Pipeline:
//  XP1: pad x, 2D FFT (y,z) per (c,d0) plane  -> g_Xyz[c][d0][k2][k3<33]
//  XP2: FFT along d0                          -> g_Xf [c][k2][k3][k1(64)]  (line-contiguous)
//  WP1: 2D FFT (y,z) per (v,d0) plane         -> g_Wyz[v][d0][k2][k3<33]
//  WP2: FFT along d0, multiply Xf, fold k1 (->32), ifft32 along k1 -> g_H[v][xs<32][k2][k3]
//  WP3: fold k2,k3 (Hermitian for k3>32), 2D ifft32, real part * 1/64^3 -> out
//
// Fold identity per axis: y[2i+1] = (1/64) * sum_{k'=0}^{31} T[k'](Y[k']-Y[k'+32]) e^{+2pi i k' i/32},
// with T[k'] = e^{+2pi i k'/64}.

__device__ float2 g_Wyz[69206016]; // 512*64*64*33
__device__ float2 g_H  [34603008]; // 512*32*64*33
__device__ float2 g_Xyz[ 4325376]; // 32*64*64*33
__device__ float2 g_Xf [ 4325376]; // 32*64*33*64

__device__ __forceinline__ float2 cmulf(float2 a, float2 b){
    return make_float2(a.x*b.x - a.y*b.y, a.x*b.y + a.y*b.x);
}
__device__ __forceinline__ float2 cadd(float2 a, float2 b){ return make_float2(a.x+b.x, a.y+b.y); }
__device__ __forceinline__ float2 csub(float2 a, float2 b){ return make_float2(a.x-b.x, a.y-b.y); }
__device__ __forceinline__ float2 cconj(float2 a){ return make_float2(a.x, -a.y); }

// tw[t] = e^{-2 pi i t / 64}
__device__ __forceinline__ void build_tw(float2* tw){
    for (int t = threadIdx.x; t < 64; t += blockDim.x) {
        float s, c;
        sincospif(-(float)t / 32.0f, &s, &c);
        tw[t] = make_float2(c, s);
    }
}

// In-place radix-2 DIT FFT on nlines lines of N points in shared memory.
// Element (line l, pos p) at buf[l*lstride + p*estride].
// Forward (INV=false): sum a[n] e^{-2pi i nk/N}. Inverse (INV=true): e^{+...}, unnormalized.
// Caller must __syncthreads() after writing buf; this function syncs internally and on exit.
template<int N, int LOG2N, bool INV>
__device__ void fft_lines(float2* buf, int nlines, int lstride, int estride, const float2* tw){
    const int tid = threadIdx.x, nt = blockDim.x;
    // bit-reversal permutation
    for (int t = tid; t < nlines * N; t += nt) {
        int l = t >> LOG2N, p = t & (N - 1);
        int r = (int)(__brev((unsigned)p) >> (32 - LOG2N));
        if (r > p) {
            float2* pa = buf + l * lstride + p * estride;
            float2* pb = buf + l * lstride + r * estride;
            float2 va = *pa, vb = *pb;
            *pa = vb; *pb = va;
        }
    }
    __syncthreads();
    #pragma unroll
    for (int s = 1; s <= LOG2N; s++) {
        const int half = 1 << (s - 1);
        for (int t = tid; t < nlines * (N / 2); t += nt) {
            int l = t >> (LOG2N - 1), b = t & ((N / 2) - 1);
            int j = b & (half - 1);
            int base = (b >> (s - 1)) << s;
            float2* pa = buf + l * lstride + (base + j) * estride;
            float2* pb = pa + half * estride;
            float2 w = tw[j << (6 - s)];
            if (INV) w.y = -w.y;
            float2 u = *pa, v = cmulf(*pb, w);
            *pa = cadd(u, v);
            *pb = csub(u, v);
        }
        __syncthreads();
    }
}

// ---------------- X side ----------------

// grid (64 d0, 32 c)
__global__ void __launch_bounds__(256) k_xp1(const float* __restrict__ x){
    __shared__ float2 sbuf[64 * 65];
    __shared__ float2 stw[64];
    const int d0 = blockIdx.x, c = blockIdx.y;
    build_tw(stw);
    const bool zplane = (d0 == 0 || d0 == 63);
    for (int t = threadIdx.x; t < 4096; t += blockDim.x) {
        int d1 = t >> 6, d2 = t & 63;
        float val = 0.0f;
        if (!zplane && d1 >= 1 && d1 <= 62 && d2 >= 1 && d2 <= 62)
            val = x[(((size_t)c * 62 + (d0 - 1)) * 62 + (d1 - 1)) * 62 + (d2 - 1)];
        sbuf[d1 * 65 + d2] = make_float2(val, 0.0f);
    }
    __syncthreads();
    fft_lines<64, 6, false>(sbuf, 64, 65, 1, stw);   // along d2 -> k3
    fft_lines<64, 6, false>(sbuf, 33, 1, 65, stw);   // along d1 -> k2 (only k3<=32 lines)
    float2* dst = g_Xyz + ((size_t)c * 64 + d0) * 2112;
    for (int t = threadIdx.x; t < 2112; t += blockDim.x) {
        int k2 = t / 33, k3 = t % 33;
        dst[t] = sbuf[k2 * 65 + k3];
    }
}

// grid (64 k2, 32 c)
__global__ void __launch_bounds__(256) k_xp2(){
    __shared__ float2 sbuf[33 * 65];
    __shared__ float2 stw[64];
    const int k2 = blockIdx.x, c = blockIdx.y;
    build_tw(stw);
    const float2* src = g_Xyz + (size_t)c * 135168 + k2 * 33;
    for (int t = threadIdx.x; t < 64 * 33; t += blockDim.x) {
        int d0 = t / 33, k3 = t % 33;
        sbuf[k3 * 65 + d0] = src[(size_t)d0 * 2112 + k3];
    }
    __syncthreads();
    fft_lines<64, 6, false>(sbuf, 33, 65, 1, stw);   // along d0 -> k1
    float2* dst = g_Xf + ((size_t)c * 64 + k2) * 33 * 64;
    for (int t = threadIdx.x; t < 33 * 64; t += blockDim.x) {
        int k3 = t >> 6, k1 = t & 63;
        dst[t] = sbuf[k3 * 65 + k1];
    }
}

// ---------------- W side ----------------

// grid (64 d0, 512 v)
__global__ void __launch_bounds__(256) k_wp1(const float* __restrict__ w){
    __shared__ float2 sbuf[64 * 65];
    __shared__ float2 stw[64];
    const int d0 = blockIdx.x, v = blockIdx.y;
    build_tw(stw);
    const float* src = w + ((size_t)v * 64 + d0) * 4096;
    for (int t = threadIdx.x; t < 4096; t += blockDim.x) {
        int d1 = t >> 6, d2 = t & 63;
        sbuf[d1 * 65 + d2] = make_float2(src[t], 0.0f);
    }
    __syncthreads();
    fft_lines<64, 6, false>(sbuf, 64, 65, 1, stw);   // along d2 -> k3
    fft_lines<64, 6, false>(sbuf, 33, 1, 65, stw);   // along d1 -> k2
    float2* dst = g_Wyz + ((size_t)v * 64 + d0) * 2112;
    for (int t = threadIdx.x; t < 2112; t += blockDim.x) {
        int k2 = t / 33, k3 = t % 33;
        dst[t] = sbuf[k2 * 65 + k3];
    }
}

// grid (64 k2, 512 v): FFT along d0, multiply Xf, fold k1, ifft32 along k1 -> H
__global__ void __launch_bounds__(256) k_wp2(){
    __shared__ float2 sbuf [33 * 65];
    __shared__ float2 sfold[33 * 33];
    __shared__ float2 stw[64];
    const int k2 = blockIdx.x, v = blockIdx.y;
    const int c = v & 31;                       // v = o*32 + c
    build_tw(stw);
    const float2* src = g_Wyz + (size_t)v * 135168 + k2 * 33;
    for (int t = threadIdx.x; t < 64 * 33; t += blockDim.x) {
        int d0 = t / 33, k3 = t % 33;
        sbuf[k3 * 65 + d0] = src[(size_t)d0 * 2112 + k3];
    }
    __syncthreads();
    fft_lines<64, 6, false>(sbuf, 33, 65, 1, stw);  // along d0 -> k1
    const float2* xf = g_Xf + ((size_t)c * 64 + k2) * 33 * 64;
    for (int t = threadIdx.x; t < 33 * 32; t += blockDim.x) {
        int k3 = t >> 5, k1 = t & 31;
        float2 Ya = cmulf(sbuf[k3 * 65 + k1     ], xf[k3 * 64 + k1     ]);
        float2 Yb = cmulf(sbuf[k3 * 65 + k1 + 32], xf[k3 * 64 + k1 + 32]);
        // G[k1] = e^{+2pi i k1/64} * (Ya - Yb)
        sfold[k3 * 33 + k1] = cmulf(cconj(stw[k1]), csub(Ya, Yb));
    }
    __syncthreads();
    fft_lines<32, 5, true>(sfold, 33, 33, 1, stw);  // ifft32 along k1 -> xs
    float2* dst = g_H + (size_t)v * 67584 + k2 * 33;
    for (int t = threadIdx.x; t < 32 * 33; t += blockDim.x) {
        int xs = t / 33, k3 = t % 33;
        dst[(size_t)xs * 2112 + k3] = sfold[k3 * 33 + xs];
    }
}

// grid (31 xs, 512 v): fold k2,k3 + 2D ifft32, write real output
__global__ void __launch_bounds__(256) k_wp3(float* __restrict__ out){
    __shared__ float2 sh[64 * 33];
    __shared__ float2 sg[32 * 33];
    __shared__ float2 stw[64];
    const int xs = blockIdx.x, v = blockIdx.y;
    build_tw(stw);
    const float2* src = g_H + (size_t)v * 67584 + (size_t)xs * 2112;
    for (int t = threadIdx.x; t < 2112; t += blockDim.x) sh[t] = src[t];
    __syncthreads();
    for (int t = threadIdx.x; t < 1024; t += blockDim.x) {
        int k2 = t >> 5, k3 = t & 31;
        float2 a = csub(sh[k2 * 33 + k3], sh[(k2 + 32) * 33 + k3]);
        float2 b;
        if (k3 == 0) {
            // k3 + 32 == 32: stored directly
            b = csub(sh[k2 * 33 + 32], sh[(k2 + 32) * 33 + 32]);
        } else {
            // k3 + 32 in 33..63: H[q, kk] = conj(H[(64-q)%64, 64-kk])  (H Hermitian in (k2,k3))
            int z  = 32 - k3;                // 64 - (k3+32), in 1..31
            int q1 = (64 - k2) & 63;
            int q2 = (32 - k2) & 63;
            b = csub(cconj(sh[q1 * 33 + z]), cconj(sh[q2 * 33 + z]));
        }
        // G3 = Tz[k3] * Ty[k2] * (a - b), T[k] = e^{+2pi i k/64} = conj(tw[k])
        float2 g = cmulf(cconj(stw[k3]), cmulf(cconj(stw[k2]), csub(a, b)));
        sg[k2 * 33 + k3] = g;
    }
    __syncthreads();
    fft_lines<32, 5, true>(sg, 32, 33, 1, stw);  // ifft32 along k3 -> l
    fft_lines<32, 5, true>(sg, 32, 1, 33, stw);  // ifft32 along k2 -> j
    float* dst = out + (size_t)v * 29791 + (size_t)xs * 961;
    const float scale = 1.0f / 262144.0f;        // 1/64^3
    for (int t = threadIdx.x; t < 961; t += blockDim.x) {
        int j = t / 31, l = t % 31;
        dst[j * 31 + l] = sg[j * 33 + l].x * scale;
    }
}

extern "C" void kernel_launch(void* const* d_in, const int* in_sizes, int n_in,
                              void* d_out, int out_size){
    (void)in_sizes; (void)n_in; (void)out_size;
    const float* x = (const float*)d_in[0];
    const float* w = (const float*)d_in[1];
    float* out = (float*)d_out;

    k_xp1<<<dim3(64, 32), 256>>>(x);
    k_xp2<<<dim3(64, 32), 256>>>();
    k_wp1<<<dim3(64, 512), 256>>>(w);
    k_wp2<<<dim3(64, 512), 256>>>();
    k_wp3<<<dim3(31, 512), 256>>>(out);
}

// round 10
// speedup vs baseline: 2.3628x; 2.3628x over previous
#include <cuda_runtime.h>

// Conv3dFFT: per-channel 64^3 circular convolution via FFT, odd-index stride-2 output.
// x: (1,32,62,62,62) f32, weight: (16,32,64,64,64) f32 -> out: (16,32,31,31,31) f32
//
// Pipeline:
//  XP1: pad x, 2D FFT (y,z) per (c,d0) plane  -> g_Xyz[c][d0][k2][k3<33]
//  XP2: FFT along d0                          -> g_Xf [c][k2][k3][k1(64)]
//  WP1: 2D FFT (y,z) per (v,d0) plane         -> g_Wyz[v][d0][k2][k3<33]
//  WP2: FFT along d0, multiply Xf, fold k1 (->32), ifft32 along k1 -> g_H[v][xs<32][k2][k3]
//  WP3: fold k2,k3 (Hermitian for k3>32), 2D ifft32, real part * 1/64^3 -> out
//
// FFTs: register-resident radix-8 (64 = 8x8, 32 = 4x8), cross-lane transpose via shfl_xor.
// Shared memory touched exactly once on load and once on store per element.

__device__ float2 g_Wyz[69206016]; // 512*64*64*33
__device__ float2 g_H  [34603008]; // 512*32*64*33
__device__ float2 g_Xyz[ 4325376]; // 32*64*64*33
__device__ float2 g_Xf [ 4325376]; // 32*64*33*64

__device__ __forceinline__ float2 cmulf(float2 a, float2 b){
    return make_float2(a.x*b.x - a.y*b.y, a.x*b.y + a.y*b.x);
}
__device__ __forceinline__ float2 cadd(float2 a, float2 b){ return make_float2(a.x+b.x, a.y+b.y); }
__device__ __forceinline__ float2 csub(float2 a, float2 b){ return make_float2(a.x-b.x, a.y-b.y); }
__device__ __forceinline__ float2 cconj(float2 a){ return make_float2(a.x, -a.y); }

// a * W4^1  (fwd: -i, inv: +i)
template<bool INV>
__device__ __forceinline__ float2 mul_wi(float2 a){
    return INV ? make_float2(-a.y, a.x) : make_float2(a.y, -a.x);
}
// a * W8^1  (fwd: (1-i)/sqrt2, inv: (1+i)/sqrt2)
template<bool INV>
__device__ __forceinline__ float2 w81mul(float2 a){
    const float r = 0.70710678118654752f;
    return INV ? make_float2(r*(a.x-a.y), r*(a.x+a.y))
               : make_float2(r*(a.x+a.y), r*(a.y-a.x));
}
// a * W8^3  (fwd: -(1+i)/sqrt2, inv: -(1-i)/sqrt2)
template<bool INV>
__device__ __forceinline__ float2 w83mul(float2 a){
    const float r = 0.70710678118654752f;
    return INV ? make_float2(-r*(a.x+a.y), r*(a.x-a.y))
               : make_float2(r*(a.y-a.x), -r*(a.x+a.y));
}

// In-register DFT8, natural order in/out.
template<bool INV>
__device__ __forceinline__ void dft8(float2 a[8]){
    float2 b0=cadd(a[0],a[4]), b4=csub(a[0],a[4]);
    float2 b2=cadd(a[2],a[6]), b6=csub(a[2],a[6]);
    float2 b1=cadd(a[1],a[5]), b5=csub(a[1],a[5]);
    float2 b3=cadd(a[3],a[7]), b7=csub(a[3],a[7]);
    float2 c0=cadd(b0,b2), c2=csub(b0,b2);
    float2 t6=mul_wi<INV>(b6);
    float2 c4=cadd(b4,t6), c6=csub(b4,t6);
    float2 c1=cadd(b1,b3), c3=csub(b1,b3);
    float2 t7=mul_wi<INV>(b7);
    float2 c5=cadd(b5,t7), c7=csub(b5,t7);
    a[0]=cadd(c0,c1); a[4]=csub(c0,c1);
    float2 t3=mul_wi<INV>(c3);
    a[2]=cadd(c2,t3); a[6]=csub(c2,t3);
    float2 w5=w81mul<INV>(c5);
    a[1]=cadd(c4,w5); a[5]=csub(c4,w5);
    float2 w7=w83mul<INV>(c7);
    a[3]=cadd(c6,w7); a[7]=csub(c6,w7);
}

// In-register DFT4, natural order in/out.
template<bool INV>
__device__ __forceinline__ void dft4(float2 a[4]){
    float2 b0=cadd(a[0],a[2]), b2=csub(a[0],a[2]);
    float2 b1=cadd(a[1],a[3]), b3=csub(a[1],a[3]);
    a[0]=cadd(b0,b1); a[2]=csub(b0,b1);
    float2 t=mul_wi<INV>(b3);
    a[1]=cadd(b2,t); a[3]=csub(b2,t);
}

// 8x8 cross-lane transpose within an 8-lane team (lanes 8-aligned in the warp).
__device__ __forceinline__ void transpose8(float2 r[8], int n1){
    #pragma unroll
    for (int s = 1; s < 8; s <<= 1) {
        const bool up = (n1 & s) != 0;
        #pragma unroll
        for (int k = 0; k < 8; k++) {
            if (k & s) continue;
            const int k2 = k | s;
            float2 send = up ? r[k] : r[k2];
            float2 recv;
            recv.x = __shfl_xor_sync(0xffffffffu, send.x, s);
            recv.y = __shfl_xor_sync(0xffffffffu, send.y, s);
            if (up) r[k] = recv; else r[k2] = recv;
        }
    }
}

// tw[t] = e^{-2 pi i t / 64}
__device__ __forceinline__ void build_tw(float2* tw){
    for (int t = threadIdx.x; t < 64; t += blockDim.x) {
        float s, c;
        sincospif(-(float)t / 32.0f, &s, &c);
        tw[t] = make_float2(c, s);
    }
}

// 64-point FFT on nlines lines in smem. Teams of 8 lanes; 256 threads -> 32 teams.
// Element p of line l at buf[l*lstride + p*estride]. Forward: e^{-}, inverse: e^{+} unnormalized.
// Caller must __syncthreads() after writing buf; this syncs on exit.
template<bool INV>
__device__ void fft64_lines(float2* __restrict__ buf, int nlines, int lstride, int estride,
                            const float2* __restrict__ tw){
    const int team = (int)(threadIdx.x >> 3);
    const int n1   = (int)(threadIdx.x & 7);
    for (int base = 0; base < nlines; base += 32) {
        const int l = base + team;
        const bool act = l < nlines;
        float2* line = buf + (size_t)l * lstride;
        float2 a[8];
        #pragma unroll
        for (int m = 0; m < 8; m++) a[m] = make_float2(0.f, 0.f);
        if (act) {
            #pragma unroll
            for (int m = 0; m < 8; m++) a[m] = line[(n1 + 8*m) * estride];
        }
        dft8<INV>(a);                 // inner DFT8 over n2 -> y[n1][k2]
        float2 w1 = tw[n1];           // W64^{n1}
        if (INV) w1.y = -w1.y;
        float2 w = w1;
        #pragma unroll
        for (int k2 = 1; k2 < 8; k2++) {
            a[k2] = cmulf(a[k2], w);  // * W64^{n1*k2}
            if (k2 < 7) w = cmulf(w, w1);
        }
        transpose8(a, n1);            // lane q now holds z[n1][k2=q], n1 = reg index
        dft8<INV>(a);                 // outer DFT8 over n1 -> X[8*k1 + q]
        if (act) {
            #pragma unroll
            for (int k1 = 0; k1 < 8; k1++) line[(8*k1 + n1) * estride] = a[k1];
        }
    }
    __syncthreads();
}

// 32-point FFT on nlines lines in smem. Teams of 4 lanes; 256 threads -> 64 teams.
template<bool INV>
__device__ void fft32_lines(float2* __restrict__ buf, int nlines, int lstride, int estride,
                            const float2* __restrict__ tw){
    const int team = (int)(threadIdx.x >> 2);
    const int q    = (int)(threadIdx.x & 3);
    for (int base = 0; base < nlines; base += 64) {
        const int l = base + team;
        const bool act = l < nlines;
        float2* line = buf + (size_t)l * lstride;
        float2 u[4], v[4];
        #pragma unroll
        for (int m = 0; m < 4; m++){ u[m]=make_float2(0.f,0.f); v[m]=make_float2(0.f,0.f); }
        if (act) {
            #pragma unroll
            for (int m = 0; m < 4; m++) {
                u[m] = line[(q     + 8*m) * estride];   // n1 = q
                v[m] = line[(q + 4 + 8*m) * estride];   // n1 = q+4
            }
        }
        dft4<INV>(u); dft4<INV>(v);   // inner DFT4 over n2
        float2 wu1 = tw[2*q], wv1 = tw[2*q + 8];  // W32^{q}, W32^{q+4}
        if (INV) { wu1.y = -wu1.y; wv1.y = -wv1.y; }
        float2 wu = wu1, wv = wv1;
        #pragma unroll
        for (int k2 = 1; k2 < 4; k2++) {
            u[k2] = cmulf(u[k2], wu);
            v[k2] = cmulf(v[k2], wv);
            if (k2 < 3) { wu = cmulf(wu, wu1); wv = cmulf(wv, wv1); }
        }
        // 4x4 transpose of (u,v) pairs across the 4 lanes
        #pragma unroll
        for (int s = 1; s < 4; s <<= 1) {
            const bool up = (q & s) != 0;
            #pragma unroll
            for (int k = 0; k < 4; k++) {
                if (k & s) continue;
                const int k2i = k | s;
                float2 su = up ? u[k] : u[k2i];
                float2 sv = up ? v[k] : v[k2i];
                float2 ru, rv;
                ru.x = __shfl_xor_sync(0xffffffffu, su.x, s);
                ru.y = __shfl_xor_sync(0xffffffffu, su.y, s);
                rv.x = __shfl_xor_sync(0xffffffffu, sv.x, s);
                rv.y = __shfl_xor_sync(0xffffffffu, sv.y, s);
                if (up) { u[k] = ru; v[k] = rv; }
                else    { u[k2i] = ru; v[k2i] = rv; }
            }
        }
        // lane q holds z[j][q] = u[j], z[j+4][q] = v[j]
        float2 c[8];
        #pragma unroll
        for (int j = 0; j < 4; j++) { c[j] = u[j]; c[j+4] = v[j]; }
        dft8<INV>(c);                 // outer DFT8 over n1 -> X[4*k1 + q]
        if (act) {
            #pragma unroll
            for (int k1 = 0; k1 < 8; k1++) line[(4*k1 + q) * estride] = c[k1];
        }
    }
    __syncthreads();
}

// ---------------- X side ----------------

// grid (64 d0, 32 c)
__global__ void __launch_bounds__(256) k_xp1(const float* __restrict__ x){
    __shared__ float2 sbuf[64 * 65];
    __shared__ float2 stw[64];
    const int d0 = blockIdx.x, c = blockIdx.y;
    build_tw(stw);
    const bool zplane = (d0 == 0 || d0 == 63);
    for (int t = threadIdx.x; t < 4096; t += blockDim.x) {
        int d1 = t >> 6, d2 = t & 63;
        float val = 0.0f;
        if (!zplane && d1 >= 1 && d1 <= 62 && d2 >= 1 && d2 <= 62)
            val = x[(((size_t)c * 62 + (d0 - 1)) * 62 + (d1 - 1)) * 62 + (d2 - 1)];
        sbuf[d1 * 65 + d2] = make_float2(val, 0.0f);
    }
    __syncthreads();
    fft64_lines<false>(sbuf, 64, 65, 1, stw);   // along d2 -> k3
    fft64_lines<false>(sbuf, 33, 1, 65, stw);   // along d1 -> k2 (only k3<=32 lines)
    float2* dst = g_Xyz + ((size_t)c * 64 + d0) * 2112;
    for (int t = threadIdx.x; t < 2112; t += blockDim.x) {
        int k2 = t / 33, k3 = t % 33;
        dst[t] = sbuf[k2 * 65 + k3];
    }
}

// grid (64 k2, 32 c)
__global__ void __launch_bounds__(256) k_xp2(){
    __shared__ float2 sbuf[33 * 65];
    __shared__ float2 stw[64];
    const int k2 = blockIdx.x, c = blockIdx.y;
    build_tw(stw);
    const float2* src = g_Xyz + (size_t)c * 135168 + k2 * 33;
    for (int t = threadIdx.x; t < 64 * 33; t += blockDim.x) {
        int d0 = t / 33, k3 = t % 33;
        sbuf[k3 * 65 + d0] = src[(size_t)d0 * 2112 + k3];
    }
    __syncthreads();
    fft64_lines<false>(sbuf, 33, 65, 1, stw);   // along d0 -> k1
    float2* dst = g_Xf + ((size_t)c * 64 + k2) * 33 * 64;
    for (int t = threadIdx.x; t < 33 * 64; t += blockDim.x) {
        int k3 = t >> 6, k1 = t & 63;
        dst[t] = sbuf[k3 * 65 + k1];
    }
}

// ---------------- W side ----------------

// grid (64 d0, 512 v)
__global__ void __launch_bounds__(256) k_wp1(const float* __restrict__ w){
    __shared__ float2 sbuf[64 * 65];
    __shared__ float2 stw[64];
    const int d0 = blockIdx.x, v = blockIdx.y;
    build_tw(stw);
    const float* src = w + ((size_t)v * 64 + d0) * 4096;
    for (int t = threadIdx.x; t < 4096; t += blockDim.x) {
        int d1 = t >> 6, d2 = t & 63;
        sbuf[d1 * 65 + d2] = make_float2(src[t], 0.0f);
    }
    __syncthreads();
    fft64_lines<false>(sbuf, 64, 65, 1, stw);   // along d2 -> k3
    fft64_lines<false>(sbuf, 33, 1, 65, stw);   // along d1 -> k2
    float2* dst = g_Wyz + ((size_t)v * 64 + d0) * 2112;
    for (int t = threadIdx.x; t < 2112; t += blockDim.x) {
        int k2 = t / 33, k3 = t % 33;
        dst[t] = sbuf[k2 * 65 + k3];
    }
}

// grid (64 k2, 512 v): FFT along d0, multiply Xf, fold k1, ifft32 along k1 -> H
__global__ void __launch_bounds__(256) k_wp2(){
    __shared__ float2 sbuf [33 * 65];
    __shared__ float2 sfold[33 * 33];
    __shared__ float2 stw[64];
    const int k2 = blockIdx.x, v = blockIdx.y;
    const int c = v & 31;                       // v = o*32 + c
    build_tw(stw);
    const float2* src = g_Wyz + (size_t)v * 135168 + k2 * 33;
    for (int t = threadIdx.x; t < 64 * 33; t += blockDim.x) {
        int d0 = t / 33, k3 = t % 33;
        sbuf[k3 * 65 + d0] = src[(size_t)d0 * 2112 + k3];
    }
    __syncthreads();
    fft64_lines<false>(sbuf, 33, 65, 1, stw);   // along d0 -> k1
    const float2* xf = g_Xf + ((size_t)c * 64 + k2) * 33 * 64;
    for (int t = threadIdx.x; t < 33 * 32; t += blockDim.x) {
        int k3 = t >> 5, k1 = t & 31;
        float2 Ya = cmulf(sbuf[k3 * 65 + k1     ], xf[k3 * 64 + k1     ]);
        float2 Yb = cmulf(sbuf[k3 * 65 + k1 + 32], xf[k3 * 64 + k1 + 32]);
        // G[k1] = e^{+2pi i k1/64} * (Ya - Yb)
        sfold[k3 * 33 + k1] = cmulf(cconj(stw[k1]), csub(Ya, Yb));
    }
    __syncthreads();
    fft32_lines<true>(sfold, 33, 33, 1, stw);   // ifft32 along k1 -> xs
    float2* dst = g_H + (size_t)v * 67584 + k2 * 33;
    for (int t = threadIdx.x; t < 32 * 33; t += blockDim.x) {
        int xs = t / 33, k3 = t % 33;
        dst[(size_t)xs * 2112 + k3] = sfold[k3 * 33 + xs];
    }
}

// grid (31 xs, 512 v): fold k2,k3 + 2D ifft32, write real output
__global__ void __launch_bounds__(256) k_wp3(float* __restrict__ out){
    __shared__ float2 sh[64 * 33];
    __shared__ float2 sg[32 * 33];
    __shared__ float2 stw[64];
    const int xs = blockIdx.x, v = blockIdx.y;
    build_tw(stw);
    const float2* src = g_H + (size_t)v * 67584 + (size_t)xs * 2112;
    for (int t = threadIdx.x; t < 2112; t += blockDim.x) sh[t] = src[t];
    __syncthreads();
    for (int t = threadIdx.x; t < 1024; t += blockDim.x) {
        int k2 = t >> 5, k3 = t & 31;
        float2 a = csub(sh[k2 * 33 + k3], sh[(k2 + 32) * 33 + k3]);
        float2 b;
        if (k3 == 0) {
            b = csub(sh[k2 * 33 + 32], sh[(k2 + 32) * 33 + 32]);
        } else {
            int z  = 32 - k3;
            int q1 = (64 - k2) & 63;
            int q2 = (32 - k2) & 63;
            b = csub(cconj(sh[q1 * 33 + z]), cconj(sh[q2 * 33 + z]));
        }
        float2 g = cmulf(cconj(stw[k3]), cmulf(cconj(stw[k2]), csub(a, b)));
        sg[k2 * 33 + k3] = g;
    }
    __syncthreads();
    fft32_lines<true>(sg, 32, 33, 1, stw);  // ifft32 along k3 -> l
    fft32_lines<true>(sg, 32, 1, 33, stw);  // ifft32 along k2 -> j
    float* dst = out + (size_t)v * 29791 + (size_t)xs * 961;
    const float scale = 1.0f / 262144.0f;   // 1/64^3
    for (int t = threadIdx.x; t < 961; t += blockDim.x) {
        int j = t / 31, l = t % 31;
        dst[j * 31 + l] = sg[j * 33 + l].x * scale;
    }
}

extern "C" void kernel_launch(void* const* d_in, const int* in_sizes, int n_in,
                              void* d_out, int out_size){
    (void)in_sizes; (void)n_in; (void)out_size;
    const float* x = (const float*)d_in[0];
    const float* w = (const float*)d_in[1];
    float* out = (float*)d_out;

    k_xp1<<<dim3(64, 32), 256>>>(x);
    k_xp2<<<dim3(64, 32), 256>>>();
    k_wp1<<<dim3(64, 512), 256>>>(w);
    k_wp2<<<dim3(64, 512), 256>>>();
    k_wp3<<<dim3(31, 512), 256>>>(out);
}

// round 11
// speedup vs baseline: 2.4820x; 1.0504x over previous
#include <cuda_runtime.h>

// Conv3dFFT: per-channel 64^3 circular convolution via FFT, odd-index stride-2 output.
// x: (1,32,62,62,62) f32, weight: (16,32,64,64,64) f32 -> out: (16,32,31,31,31) f32
//
// Pipeline:
//  XP1: pad x, 2D FFT (y,z) per (c,d0) plane  -> g_Xyz[c][d0][k2][k3<33]
//  XP2: FFT along d0                          -> g_Xf [c][k2][k3][k1(64)]
//  WP1: 2D FFT (y,z) per (v,d0) plane         -> g_Wyz[v][d0][k2][k3<33]
//  WP2: per k2-PAIR (k2', k2'+32): FFT along d0 (both), multiply Xf, fold k2 AND k1,
//       ifft32 along k1 -> g_H[v][xs<32][k2'<32][k3<33]   (half the old H)
//  WP3: fold k3 via F-conjugate identity, 2D ifft32, real part * 1/64^3 -> out
//
// Fold identity per axis: y[2i+1] = (1/N) sum_{k'} T[k'](Y[k']-Y[k'+N/2]) e^{+2pi i k' i/(N/2)},
// T[k'] = e^{+2pi i k'/N}. After the k2 fold, the k3-fold partner satisfies
//   F[k2'][k3'+32] = conj(F[(32-k2')&31][32-k3'])  (k3' in 1..31),   F[k2'][32] stored directly.
//
// FFTs: register-resident radix-8 (64 = 8x8, 32 = 4x8), shfl_xor transposes,
// compile-time smem strides, warp-per-row global loops (no div/mod).

__device__ float2 g_Wyz[69206016]; // 512*64*64*33
__device__ float2 g_H  [17301504]; // 512*32*32*33
__device__ float2 g_Xyz[ 4325376]; // 32*64*64*33
__device__ float2 g_Xf [ 4325376]; // 32*64*33*64

__device__ __forceinline__ float2 cmulf(float2 a, float2 b){
    return make_float2(a.x*b.x - a.y*b.y, a.x*b.y + a.y*b.x);
}
__device__ __forceinline__ float2 cadd(float2 a, float2 b){ return make_float2(a.x+b.x, a.y+b.y); }
__device__ __forceinline__ float2 csub(float2 a, float2 b){ return make_float2(a.x-b.x, a.y-b.y); }
__device__ __forceinline__ float2 cconj(float2 a){ return make_float2(a.x, -a.y); }

template<bool INV>
__device__ __forceinline__ float2 mul_wi(float2 a){
    return INV ? make_float2(-a.y, a.x) : make_float2(a.y, -a.x);
}
template<bool INV>
__device__ __forceinline__ float2 w81mul(float2 a){
    const float r = 0.70710678118654752f;
    return INV ? make_float2(r*(a.x-a.y), r*(a.x+a.y))
               : make_float2(r*(a.x+a.y), r*(a.y-a.x));
}
template<bool INV>
__device__ __forceinline__ float2 w83mul(float2 a){
    const float r = 0.70710678118654752f;
    return INV ? make_float2(-r*(a.x+a.y), r*(a.x-a.y))
               : make_float2(r*(a.y-a.x), -r*(a.x+a.y));
}

template<bool INV>
__device__ __forceinline__ void dft8(float2 a[8]){
    float2 b0=cadd(a[0],a[4]), b4=csub(a[0],a[4]);
    float2 b2=cadd(a[2],a[6]), b6=csub(a[2],a[6]);
    float2 b1=cadd(a[1],a[5]), b5=csub(a[1],a[5]);
    float2 b3=cadd(a[3],a[7]), b7=csub(a[3],a[7]);
    float2 c0=cadd(b0,b2), c2=csub(b0,b2);
    float2 t6=mul_wi<INV>(b6);
    float2 c4=cadd(b4,t6), c6=csub(b4,t6);
    float2 c1=cadd(b1,b3), c3=csub(b1,b3);
    float2 t7=mul_wi<INV>(b7);
    float2 c5=cadd(b5,t7), c7=csub(b5,t7);
    a[0]=cadd(c0,c1); a[4]=csub(c0,c1);
    float2 t3=mul_wi<INV>(c3);
    a[2]=cadd(c2,t3); a[6]=csub(c2,t3);
    float2 w5=w81mul<INV>(c5);
    a[1]=cadd(c4,w5); a[5]=csub(c4,w5);
    float2 w7=w83mul<INV>(c7);
    a[3]=cadd(c6,w7); a[7]=csub(c6,w7);
}

template<bool INV>
__device__ __forceinline__ void dft4(float2 a[4]){
    float2 b0=cadd(a[0],a[2]), b2=csub(a[0],a[2]);
    float2 b1=cadd(a[1],a[3]), b3=csub(a[1],a[3]);
    a[0]=cadd(b0,b1); a[2]=csub(b0,b1);
    float2 t=mul_wi<INV>(b3);
    a[1]=cadd(b2,t); a[3]=csub(b2,t);
}

__device__ __forceinline__ void transpose8(float2 r[8], int n1){
    #pragma unroll
    for (int s = 1; s < 8; s <<= 1) {
        const bool up = (n1 & s) != 0;
        #pragma unroll
        for (int k = 0; k < 8; k++) {
            if (k & s) continue;
            const int k2 = k | s;
            float2 send = up ? r[k] : r[k2];
            float2 recv;
            recv.x = __shfl_xor_sync(0xffffffffu, send.x, s);
            recv.y = __shfl_xor_sync(0xffffffffu, send.y, s);
            if (up) r[k] = recv; else r[k2] = recv;
        }
    }
}

// tw[t] = e^{-2 pi i t / 64}
__device__ __forceinline__ void build_tw(float2* tw){
    for (int t = threadIdx.x; t < 64; t += blockDim.x) {
        float s, c;
        sincospif(-(float)t / 32.0f, &s, &c);
        tw[t] = make_float2(c, s);
    }
}

// 64-point FFT, compile-time strides. Teams of 8 lanes; 256 threads -> 32 teams.
template<bool INV, int LSTRIDE, int ESTRIDE>
__device__ void fft64_lines(float2* __restrict__ buf, int nlines, const float2* __restrict__ tw){
    const int team = (int)(threadIdx.x >> 3);
    const int n1   = (int)(threadIdx.x & 7);
    for (int base = 0; base < nlines; base += 32) {
        const int l = base + team;
        const bool act = l < nlines;
        float2* line = buf + l * LSTRIDE;
        float2 a[8];
        #pragma unroll
        for (int m = 0; m < 8; m++) a[m] = make_float2(0.f, 0.f);
        if (act) {
            #pragma unroll
            for (int m = 0; m < 8; m++) a[m] = line[(n1 + 8*m) * ESTRIDE];
        }
        dft8<INV>(a);
        float2 w1 = tw[n1];
        if (INV) w1.y = -w1.y;
        float2 w = w1;
        #pragma unroll
        for (int k2 = 1; k2 < 8; k2++) {
            a[k2] = cmulf(a[k2], w);
            if (k2 < 7) w = cmulf(w, w1);
        }
        transpose8(a, n1);
        dft8<INV>(a);
        if (act) {
            #pragma unroll
            for (int k1 = 0; k1 < 8; k1++) line[(8*k1 + n1) * ESTRIDE] = a[k1];
        }
    }
    __syncthreads();
}

// 32-point FFT, compile-time strides. Teams of 4 lanes; 256 threads -> 64 teams.
template<bool INV, int LSTRIDE, int ESTRIDE>
__device__ void fft32_lines(float2* __restrict__ buf, int nlines, const float2* __restrict__ tw){
    const int team = (int)(threadIdx.x >> 2);
    const int q    = (int)(threadIdx.x & 3);
    for (int base = 0; base < nlines; base += 64) {
        const int l = base + team;
        const bool act = l < nlines;
        float2* line = buf + l * LSTRIDE;
        float2 u[4], v[4];
        #pragma unroll
        for (int m = 0; m < 4; m++){ u[m]=make_float2(0.f,0.f); v[m]=make_float2(0.f,0.f); }
        if (act) {
            #pragma unroll
            for (int m = 0; m < 4; m++) {
                u[m] = line[(q     + 8*m) * ESTRIDE];
                v[m] = line[(q + 4 + 8*m) * ESTRIDE];
            }
        }
        dft4<INV>(u); dft4<INV>(v);
        float2 wu1 = tw[2*q], wv1 = tw[2*q + 8];
        if (INV) { wu1.y = -wu1.y; wv1.y = -wv1.y; }
        float2 wu = wu1, wv = wv1;
        #pragma unroll
        for (int k2 = 1; k2 < 4; k2++) {
            u[k2] = cmulf(u[k2], wu);
            v[k2] = cmulf(v[k2], wv);
            if (k2 < 3) { wu = cmulf(wu, wu1); wv = cmulf(wv, wv1); }
        }
        #pragma unroll
        for (int s = 1; s < 4; s <<= 1) {
            const bool up = (q & s) != 0;
            #pragma unroll
            for (int k = 0; k < 4; k++) {
                if (k & s) continue;
                const int k2i = k | s;
                float2 su = up ? u[k] : u[k2i];
                float2 sv = up ? v[k] : v[k2i];
                float2 ru, rv;
                ru.x = __shfl_xor_sync(0xffffffffu, su.x, s);
                ru.y = __shfl_xor_sync(0xffffffffu, su.y, s);
                rv.x = __shfl_xor_sync(0xffffffffu, sv.x, s);
                rv.y = __shfl_xor_sync(0xffffffffu, sv.y, s);
                if (up) { u[k] = ru; v[k] = rv; }
                else    { u[k2i] = ru; v[k2i] = rv; }
            }
        }
        float2 c[8];
        #pragma unroll
        for (int j = 0; j < 4; j++) { c[j] = u[j]; c[j+4] = v[j]; }
        dft8<INV>(c);
        if (act) {
            #pragma unroll
            for (int k1 = 0; k1 < 8; k1++) line[(4*k1 + q) * ESTRIDE] = c[k1];
        }
    }
    __syncthreads();
}

// ---------------- X side ----------------

// grid (64 d0, 32 c)
__global__ void __launch_bounds__(256) k_xp1(const float* __restrict__ x){
    __shared__ float2 sbuf[64 * 65];
    __shared__ float2 stw[64];
    const int d0 = blockIdx.x, c = blockIdx.y;
    const int wid = threadIdx.x >> 5, lane = threadIdx.x & 31;
    build_tw(stw);
    const bool zplane = (d0 == 0 || d0 == 63);
    for (int t = threadIdx.x; t < 4096; t += blockDim.x) {
        int d1 = t >> 6, d2 = t & 63;
        float val = 0.0f;
        if (!zplane && d1 >= 1 && d1 <= 62 && d2 >= 1 && d2 <= 62)
            val = x[(((size_t)c * 62 + (d0 - 1)) * 62 + (d1 - 1)) * 62 + (d2 - 1)];
        sbuf[d1 * 65 + d2] = make_float2(val, 0.0f);
    }
    __syncthreads();
    fft64_lines<false, 65, 1>(sbuf, 64, stw);   // along d2 -> k3
    fft64_lines<false, 1, 65>(sbuf, 33, stw);   // along d1 -> k2 (only k3<=32 lines)
    float2* dst = g_Xyz + ((size_t)c * 64 + d0) * 2112;
    for (int k2 = wid; k2 < 64; k2 += 8)
        for (int k3 = lane; k3 < 33; k3 += 32)
            dst[k2 * 33 + k3] = sbuf[k2 * 65 + k3];
}

// grid (64 k2, 32 c)
__global__ void __launch_bounds__(256) k_xp2(){
    __shared__ float2 sbuf[33 * 65];
    __shared__ float2 stw[64];
    const int k2 = blockIdx.x, c = blockIdx.y;
    const int wid = threadIdx.x >> 5, lane = threadIdx.x & 31;
    build_tw(stw);
    const float2* src = g_Xyz + (size_t)c * 135168 + k2 * 33;
    for (int d0 = wid; d0 < 64; d0 += 8)
        for (int k3 = lane; k3 < 33; k3 += 32)
            sbuf[k3 * 65 + d0] = src[(size_t)d0 * 2112 + k3];
    __syncthreads();
    fft64_lines<false, 65, 1>(sbuf, 33, stw);   // along d0 -> k1
    float2* dst = g_Xf + ((size_t)c * 64 + k2) * 2112;
    for (int t = threadIdx.x; t < 2112; t += blockDim.x) {
        int k3 = t >> 6, k1 = t & 63;
        dst[t] = sbuf[k3 * 65 + k1];
    }
}

// ---------------- W side ----------------

// grid (64 d0, 512 v)
__global__ void __launch_bounds__(256) k_wp1(const float* __restrict__ w){
    __shared__ float2 sbuf[64 * 65];
    __shared__ float2 stw[64];
    const int d0 = blockIdx.x, v = blockIdx.y;
    const int wid = threadIdx.x >> 5, lane = threadIdx.x & 31;
    build_tw(stw);
    const float* src = w + ((size_t)v * 64 + d0) * 4096;
    for (int t = threadIdx.x; t < 4096; t += blockDim.x) {
        int d1 = t >> 6, d2 = t & 63;
        sbuf[d1 * 65 + d2] = make_float2(src[t], 0.0f);
    }
    __syncthreads();
    fft64_lines<false, 65, 1>(sbuf, 64, stw);   // along d2 -> k3
    fft64_lines<false, 1, 65>(sbuf, 33, stw);   // along d1 -> k2
    float2* dst = g_Wyz + ((size_t)v * 64 + d0) * 2112;
    for (int k2 = wid; k2 < 64; k2 += 8)
        for (int k3 = lane; k3 < 33; k3 += 32)
            dst[k2 * 33 + k3] = sbuf[k2 * 65 + k3];
}

// grid (32 k2-pairs, 512 v): FFT along d0 for k2' and k2'+32, multiply Xf,
// fold k2 AND k1, ifft32 along k1 -> g_H[v][xs][k2'][k3]
__global__ void __launch_bounds__(256) k_wp2(){
    __shared__ float2 sA[33 * 65];
    __shared__ float2 sB[33 * 65];
    __shared__ float2 sfold[33 * 33];
    __shared__ float2 stw[64];
    const int k2 = blockIdx.x;                  // k2' in 0..31
    const int v  = blockIdx.y;
    const int c  = v & 31;                      // v = o*32 + c
    const int wid = threadIdx.x >> 5, lane = threadIdx.x & 31;
    build_tw(stw);
    const float2* srcA = g_Wyz + (size_t)v * 135168 + k2 * 33;
    const float2* srcB = srcA + 32 * 33;        // slice k2'+32
    for (int d0 = wid; d0 < 64; d0 += 8)
        for (int k3 = lane; k3 < 33; k3 += 32) {
            sA[k3 * 65 + d0] = srcA[(size_t)d0 * 2112 + k3];
            sB[k3 * 65 + d0] = srcB[(size_t)d0 * 2112 + k3];
        }
    __syncthreads();
    fft64_lines<false, 65, 1>(sA, 33, stw);     // along d0 -> k1 (slice k2')
    fft64_lines<false, 65, 1>(sB, 33, stw);     // along d0 -> k1 (slice k2'+32)
    const float2* xfA = g_Xf + ((size_t)c * 64 + k2) * 2112;
    const float2* xfB = xfA + 32 * 2112;
    const float2 ty = cconj(stw[k2]);           // Ty[k2'] = e^{+2pi i k2'/64}
    for (int t = threadIdx.x; t < 1056; t += blockDim.x) {
        int k3 = t >> 5, k1 = t & 31;
        float2 A1 = cmulf(sA[k3 * 65 + k1     ], xfA[k3 * 64 + k1     ]);
        float2 A2 = cmulf(sA[k3 * 65 + k1 + 32], xfA[k3 * 64 + k1 + 32]);
        float2 B1 = cmulf(sB[k3 * 65 + k1     ], xfB[k3 * 64 + k1     ]);
        float2 B2 = cmulf(sB[k3 * 65 + k1 + 32], xfB[k3 * 64 + k1 + 32]);
        // k2 fold (A-B), k1 fold ((.)_k1 - (.)_{k1+32}), twiddles Ty[k2']*T1[k1]
        float2 d = csub(csub(A1, B1), csub(A2, B2));
        sfold[k3 * 33 + k1] = cmulf(cconj(stw[k1]), cmulf(ty, d));
    }
    __syncthreads();
    fft32_lines<true, 33, 1>(sfold, 33, stw);   // ifft32 along k1 -> xs (all 33 k3 lines)
    float2* dst = g_H + (size_t)v * 33792 + k2 * 33;   // [v][xs][k2'][k3]
    for (int xs = wid; xs < 32; xs += 8)
        for (int k3 = lane; k3 < 33; k3 += 32)
            dst[(size_t)xs * 1056 + k3] = sfold[k3 * 33 + xs];
}

// grid (31 xs, 512 v): fold k3 via F-conjugate identity, 2D ifft32, write real output
__global__ void __launch_bounds__(256) k_wp3(float* __restrict__ out){
    __shared__ float2 sh[32 * 33];
    __shared__ float2 sg[32 * 33];
    __shared__ float2 stw[64];
    const int xs = blockIdx.x, v = blockIdx.y;
    build_tw(stw);
    const float2* src = g_H + (size_t)v * 33792 + (size_t)xs * 1056;
    for (int t = threadIdx.x; t < 1056; t += blockDim.x) sh[t] = src[t];
    __syncthreads();
    for (int t = threadIdx.x; t < 1024; t += blockDim.x) {
        int k2 = t >> 5, k3 = t & 31;          // k2', k3' in 0..31
        float2 F = sh[k2 * 33 + k3];
        float2 b;
        if (k3 == 0) {
            b = sh[k2 * 33 + 32];              // F[k2'][32] stored directly
        } else {
            b = cconj(sh[((32 - k2) & 31) * 33 + (32 - k3)]);
        }
        // G = Tz[k3'] * (F[k3'] - F[k3'+32])
        sg[k2 * 33 + k3] = cmulf(cconj(stw[k3]), csub(F, b));
    }
    __syncthreads();
    fft32_lines<true, 33, 1>(sg, 32, stw);  // ifft32 along k3 -> l
    fft32_lines<true, 1, 33>(sg, 32, stw);  // ifft32 along k2 -> j
    float* dst = out + (size_t)v * 29791 + (size_t)xs * 961;
    const float scale = 1.0f / 262144.0f;   // 1/64^3
    for (int t = threadIdx.x; t < 961; t += blockDim.x) {
        int j = t / 31, l = t % 31;
        dst[j * 31 + l] = sg[j * 33 + l].x * scale;
    }
}

extern "C" void kernel_launch(void* const* d_in, const int* in_sizes, int n_in,
                              void* d_out, int out_size){
    (void)in_sizes; (void)n_in; (void)out_size;
    const float* x = (const float*)d_in[0];
    const float* w = (const float*)d_in[1];
    float* out = (float*)d_out;

    k_xp1<<<dim3(64, 32), 256>>>(x);
    k_xp2<<<dim3(64, 32), 256>>>();
    k_wp1<<<dim3(64, 512), 256>>>(w);
    k_wp2<<<dim3(32, 512), 256>>>();
    k_wp3<<<dim3(31, 512), 256>>>(out);
}